// round 17
// baseline (speedup 1.0000x reference)
#include <cuda_runtime.h>
#include <math.h>

#define Bc 4
#define Nc 100000
#define Kc 128
#define Q_MIN 0.5f
#define HUBER_D 2.0f
#define EPS_CLIP 1e-4f

#define GRID_N ((Nc + 255) / 256)            // 391
#define TOTAL_BLOCKS (GRID_N * Bc)           // 1564

typedef unsigned long long ull;

// ---------------- device scratch (zero at load; finalizer re-zeros) ----------
__device__ ull          g_cand[Bc * Kc];     // packed (beta_bits<<32)|(~n)
__device__ float4       g_obj[Bc * Kc];      // x, y, q_alpha*exists, 0
__device__ float        g_sumq[Bc];
__device__ double       g_acc[10];           // 0=att 1=rep 2=nb 3=nc 4=ps 5=pE 6=pPos 7=pT 8=exs 9=bos
__device__ unsigned int g_done;

__device__ __forceinline__ float sqa(float x) {            // MUFU.SQRT
    float r; asm("sqrt.approx.f32 %0, %1;" : "=f"(r) : "f"(x)); return r;
}
__device__ __forceinline__ float clipb(float b) {
    return fminf(fmaxf(b, EPS_CLIP), 1.0f - EPS_CLIP);
}
// atanh(x) = 0.34657359*log2((1+x)/(1-x)); x in [1e-4, 1-1e-4]
__device__ __forceinline__ float fast_atanh(float x) {
    float r = __fdividef(1.0f + x, 1.0f - x);
    return 0.34657359f * __log2f(r);
}

// ---------------- kernel 1: segment argmax, one hit per thread ----------------
__global__ void __launch_bounds__(256)
k_argmax(const float* __restrict__ beta,
         const int*   __restrict__ t_idx) {
    __shared__ ull sc[Kc];
    const int b = blockIdx.y;
    const int t = threadIdx.x;
    if (t < Kc) sc[t] = 0ULL;
    __syncthreads();

    const int n = blockIdx.x * 256 + t;
    if (n < Nc) {                        // both loads issue before any dependency
        const int   ti = t_idx[b * Nc + n];
        const float bc = clipb(beta[b * Nc + n]);
        if (ti > 0) {
            ull key = ((ull)__float_as_uint(bc) << 32)
                    | (ull)(0xFFFFFFFFu - (unsigned int)n);
            atomicMax(&sc[ti - 1], key);
        }
    }
    __syncthreads();
    if (t < Kc) {   // flush block-local maxima (spread global atomics)
        ull k = sc[t];
        if (k != 0ULL) atomicMax(&g_cand[b * Kc + t], k);
    }
}

// ---------------- kernel 1.5: build condensation points ONCE ------------------
__global__ void __launch_bounds__(512)
k_prep(const float* __restrict__ beta,
       const float* __restrict__ ccoords) {
    __shared__ float sq[512];
    __shared__ float sred[2][16];
    const int t = threadIdx.x;          // t = b*128 + k
    const int b = t >> 7;

    ull key = g_cand[t];
    float4 o = make_float4(0.f, 0.f, 0.f, 0.f);
    float exf = 0.f, bobj = 0.f;
    if (key != 0ULL) {
        unsigned int nn = 0xFFFFFFFFu - (unsigned int)key;
        int ii = b * Nc + (int)nn;
        float bc = clipb(beta[ii]);
        float a  = fast_atanh(bc);
        float2 c = ((const float2*)ccoords)[ii];
        o = make_float4(c.x, c.y, fmaf(a, a, Q_MIN), 0.f);
        exf  = 1.f;
        bobj = 1.f - bc;
    }
    g_obj[t] = o;

    // per-batch sum of q_alpha
    sq[t] = o.z;
    __syncthreads();
    #pragma unroll
    for (int off = 64; off >= 1; off >>= 1) {
        if ((t & 127) < off) sq[t] += sq[t + off];
        __syncthreads();
    }
    if ((t & 127) == 0) g_sumq[b] = sq[t];

    // sums of exists / (1-beta_alpha)
    float e = exf, bo = bobj;
    #pragma unroll
    for (int off = 16; off > 0; off >>= 1) {
        e  += __shfl_down_sync(0xFFFFFFFFu, e, off);
        bo += __shfl_down_sync(0xFFFFFFFFu, bo, off);
    }
    int wid = t >> 5, lid = t & 31;
    if (lid == 0) { sred[0][wid] = e; sred[1][wid] = bo; }
    __syncthreads();
    if (t == 0) {
        float es = 0.f, bs = 0.f;
        #pragma unroll
        for (int w = 0; w < 16; ++w) { es += sred[0][w]; bs += sred[1][w]; }
        g_acc[8] = (double)es;
        g_acc[9] = (double)bs;
    }
}

// ---------------- kernel 2: pair loop + payload + fused finalize --------------
__global__ void __launch_bounds__(256)
k_pair(const float* __restrict__ beta,
       const float* __restrict__ ccoords,
       const int*   __restrict__ t_idx,
       const float* __restrict__ pred_energy,
       const float* __restrict__ pred_pos,
       const float* __restrict__ pred_time,
       const float* __restrict__ t_energy,
       const float* __restrict__ t_pos,
       const float* __restrict__ t_time,
       float*       __restrict__ out) {
    __shared__ float sx[Kc], sy[Kc], sq[Kc];
    __shared__ float sr[8][8];
    __shared__ bool  s_last;

    const int b = blockIdx.y;
    const int t = threadIdx.x;

    if (t < Kc) {
        float4 o = g_obj[b * Kc + t];
        sx[t] = o.x; sy[t] = o.y; sq[t] = o.z;
    }
    const float sumq = g_sumq[b];
    __syncthreads();

    float att = 0.f, rep = 0.f, nb = 0.f, ncnt = 0.f;
    float ps = 0.f, pes = 0.f, pps = 0.f, pts = 0.f;
    const int n = blockIdx.x * 256 + t;
    if (n < Nc) {
        const int i = b * Nc + n;
        // front-batched loads — hidden under the 32-iteration MUFU loop below
        const float bc0 = beta[i];
        const int   ti  = t_idx[i];
        const float2 xc = ((const float2*)ccoords)[i];
        const float pe  = pred_energy[i];
        const float te  = t_energy[i];
        const float2 pp2 = ((const float2*)pred_pos)[i];
        const float2 tp2 = ((const float2*)t_pos)[i];
        const float pt  = pred_time[i];
        const float tt  = t_time[i];

        const float bc = clipb(bc0);
        const float a  = fast_atanh(bc);
        const float q  = fmaf(a, a, Q_MIN);
        const float cx = xc.x, cy = xc.y;

        const float4* px = (const float4*)sx;
        const float4* py = (const float4*)sy;
        const float4* pq = (const float4*)sq;

        float r0 = 0.f, r1 = 0.f, r2 = 0.f, r3 = 0.f;
        #pragma unroll 8
        for (int jj = 0; jj < Kc / 4; ++jj) {
            float4 xv = px[jj], yv = py[jj], qv = pq[jj];
            float dx, dy, d2;
            dx = cx - xv.x; dy = cy - yv.x; d2 = fmaf(dx, dx, dy * dy);
            r0 = fmaf(qv.x, sqa(fminf(d2, 1.0f)), r0);
            dx = cx - xv.y; dy = cy - yv.y; d2 = fmaf(dx, dx, dy * dy);
            r1 = fmaf(qv.y, sqa(fminf(d2, 1.0f)), r1);
            dx = cx - xv.z; dy = cy - yv.z; d2 = fmaf(dx, dx, dy * dy);
            r2 = fmaf(qv.z, sqa(fminf(d2, 1.0f)), r2);
            dx = cx - xv.w; dy = cy - yv.w; d2 = fmaf(dx, dx, dy * dy);
            r3 = fmaf(qv.w, sqa(fminf(d2, 1.0f)), r3);
        }
        float total = sumq - ((r0 + r1) + (r2 + r3));

        const int obj = ti - 1;
        if (obj >= 0) {   // member fix + attractive term
            float ox = sx[obj], oy = sy[obj], oq = sq[obj];
            float dx = cx - ox, dy = cy - oy;
            float d2 = fmaf(dx, dx, dy * dy);
            total -= oq * (1.0f - sqa(fminf(d2, 1.0f)));
            att = q * oq * d2;
        }
        rep = q * total;

        // payload losses (values already in regs)
        float noise = (ti == 0) ? 1.0f : 0.0f;
        float p = a * a * (1.0f - noise);
        ncnt = noise;
        nb   = bc * noise;
        float de  = pe - te;
        float ade = fabsf(de);
        float hub = (ade <= HUBER_D) ? 0.5f * de * de
                                     : HUBER_D * (ade - 0.5f * HUBER_D);
        float d0 = pp2.x - tp2.x, d1 = pp2.y - tp2.y;
        float dtm = pt - tt;
        ps  = p;
        pes = p * hub;
        pps = p * (d0 * d0 + d1 * d1);
        pts = p * dtm * dtm;
    }

    // ---- block reduce 8 scalars ----
    float v[8] = {att, rep, nb, ncnt, ps, pes, pps, pts};
    #pragma unroll
    for (int off = 16; off > 0; off >>= 1)
        #pragma unroll
        for (int jj = 0; jj < 8; ++jj)
            v[jj] += __shfl_down_sync(0xFFFFFFFFu, v[jj], off);
    int wid = t >> 5, lid = t & 31;
    if (lid == 0)
        #pragma unroll
        for (int jj = 0; jj < 8; ++jj) sr[jj][wid] = v[jj];
    __syncthreads();
    if (t < 8) {
        float s = 0.f;
        #pragma unroll
        for (int w = 0; w < 8; ++w) s += sr[t][w];
        atomicAdd(&g_acc[t], (double)s);
    }
    if (t == 0) {
        __threadfence();
        unsigned int done = atomicAdd(&g_done, 1u);
        s_last = (done == (unsigned int)(TOTAL_BLOCKS - 1));
    }
    __syncthreads();
    if (!s_last) return;

    // ------------- last block: finalize + reset scratch -------------
    __threadfence();
    if (t == 0) {
        volatile double* va = g_acc;
        double ntot   = (double)(Bc * Nc);
        double L_att  = va[0] / ntot;
        double L_rep  = va[1] / ntot;
        double n_obj  = fmax(va[8], 1.0);
        double L_bobj = va[9] / n_obj;
        double n_noi  = fmax(va[3], 1.0);
        double L_noi  = va[2] / n_noi;
        double psum   = fmax(va[4], 1e-6);
        double L_e    = va[5] / psum;
        double L_p    = va[6] / psum;
        double L_t    = va[7] / psum;
        out[0] = (float)(L_att + L_rep + (L_bobj + L_noi) + L_e + L_p + L_t);
    }
    __syncthreads();
    // reset for next graph replay (globals zero at load, so call 1 is clean too)
    for (int e = t; e < Bc * Kc; e += 256) g_cand[e] = 0ULL;
    if (t < 10) g_acc[t] = 0.0;
    if (t == 0) g_done = 0u;
}

// ---------------- launch ------------------------------------------------------
extern "C" void kernel_launch(void* const* d_in, const int* in_sizes, int n_in,
                              void* d_out, int out_size) {
    const float* beta        = (const float*)d_in[0];
    const float* ccoords     = (const float*)d_in[1];
    const float* pred_energy = (const float*)d_in[2];
    const float* pred_pos    = (const float*)d_in[3];
    const float* pred_time   = (const float*)d_in[4];
    const float* t_energy    = (const float*)d_in[5];
    const float* t_pos       = (const float*)d_in[6];
    const float* t_time      = (const float*)d_in[7];
    const int*   t_idx       = (const int*)d_in[8];
    float* out = (float*)d_out;

    dim3 g1(GRID_N, Bc);
    k_argmax<<<g1, 256>>>(beta, t_idx);
    k_prep<<<1, 512>>>(beta, ccoords);
    dim3 g2(GRID_N, Bc);
    k_pair<<<g2, 256>>>(beta, ccoords, t_idx,
                        pred_energy, pred_pos, pred_time,
                        t_energy, t_pos, t_time, out);
}